// round 12
// baseline (speedup 1.0000x reference)
#include <cuda_runtime.h>
#include <math.h>
#include <stdint.h>

#define BB 64
#define TT 512
#define II 512
#define HH 1024
#define OO 512
#define MM 64
#define PP 1024
#define G3 3072
#define NB 148
#define NT 512
#define LDS_ 68

__device__ __align__(16) float g_h[2][BB * HH];
__device__ __align__(16) float g_xin[BB * II];
__device__ __align__(16) float g_gi[4][BB * G3];   // gi K-splits (K=128 each)
__device__ __align__(16) float g_gh[8][BB * G3];   // gh K-splits (K=128 each)
__device__ __align__(16) float g_cp[8][BB * OO];   // out K-splits (K=128 each)
__device__ __align__(16) float g_memT[MM * PP];
__device__ volatile unsigned g_gen;
__device__ unsigned g_cnt;

static __device__ __forceinline__ void ffma2(unsigned long long& d,
                                             unsigned long long a,
                                             unsigned long long b)
{
    asm("fma.rn.f32x2 %0, %1, %2, %0;" : "+l"(d) : "l"(a), "l"(b));
}

__device__ __forceinline__ void gsync()
{
    __syncthreads();
    __threadfence();
    if (threadIdx.x == 0) {
        unsigned my = g_gen;
        if (atomicAdd(&g_cnt, 1u) == NB - 1u) {
            atomicExch(&g_cnt, 0u);
            __threadfence();
            g_gen = my + 1u;
        } else {
            while (g_gen == my) { __nanosleep(64); }
        }
    }
    __syncthreads();
    __threadfence();
}

// ---------------------------------------------------------------------------
// 64(batch) x 128(cols) x Kc GEMM partial, 512 threads, 4x4/thread, FFMA2,
// register-double-buffered staging (128 regs available).
// ---------------------------------------------------------------------------
static __device__ __forceinline__ void gemm128(
    const float* __restrict__ X, int ldx, int xoff,
    const float* __restrict__ W, int ldw, int woff,
    int n0, int Kc, float* __restrict__ outp, int ldo,
    float* __restrict__ xs, float* __restrict__ ws)
{
    const int tid = threadIdx.x;
    const int ty  = tid & 15;        // rows ty + {0,16,32,48}
    const int tx  = tid >> 4;        // cols tx + {0,32,64,96}

    unsigned long long acc2[4][4];
    #pragma unroll
    for (int i = 0; i < 4; i++)
        #pragma unroll
        for (int j = 0; j < 4; j++) acc2[i][j] = 0ull;

    float4 ra[2], rb[4];
    #pragma unroll
    for (int q = 0; q < 2; q++) {
        int idx = tid + q * NT, r = idx >> 4, kk = (idx & 15) << 2;
        ra[q] = *(const float4*)(X + (size_t)r * ldx + xoff + kk);
    }
    #pragma unroll
    for (int q = 0; q < 4; q++) {
        int idx = tid + q * NT, r = idx >> 4, kk = (idx & 15) << 2;
        rb[q] = *(const float4*)(W + (size_t)(n0 + r) * ldw + woff + kk);
    }

    const int nch = Kc >> 6;
    for (int c = 0; c < nch; c++) {
        #pragma unroll
        for (int q = 0; q < 2; q++) {
            int idx = tid + q * NT, r = idx >> 4, kk = (idx & 15) << 2;
            *(float4*)(xs + r * LDS_ + kk) = ra[q];
        }
        #pragma unroll
        for (int q = 0; q < 4; q++) {
            int idx = tid + q * NT, r = idx >> 4, kk = (idx & 15) << 2;
            *(float4*)(ws + r * LDS_ + kk) = rb[q];
        }
        __syncthreads();

        if (c + 1 < nch) {
            int k0 = (c + 1) << 6;
            #pragma unroll
            for (int q = 0; q < 2; q++) {
                int idx = tid + q * NT, r = idx >> 4, kk = (idx & 15) << 2;
                ra[q] = *(const float4*)(X + (size_t)r * ldx + xoff + k0 + kk);
            }
            #pragma unroll
            for (int q = 0; q < 4; q++) {
                int idx = tid + q * NT, r = idx >> 4, kk = (idx & 15) << 2;
                rb[q] = *(const float4*)(W + (size_t)(n0 + r) * ldw + woff + k0 + kk);
            }
        }

        const float* x0 = xs + ty * LDS_;
        const float* w0 = ws + tx * LDS_;
        #pragma unroll
        for (int k4 = 0; k4 < 16; k4++) {
            float4 xv[4];
            #pragma unroll
            for (int i = 0; i < 4; i++)
                xv[i] = *(const float4*)(x0 + i * 16 * LDS_ + k4 * 4);
            #pragma unroll
            for (int j = 0; j < 4; j++) {
                float4 wv = *(const float4*)(w0 + j * 32 * LDS_ + k4 * 4);
                unsigned long long wlo = *(unsigned long long*)&wv.x;
                unsigned long long whi = *(unsigned long long*)&wv.z;
                #pragma unroll
                for (int i = 0; i < 4; i++) {
                    ffma2(acc2[i][j], *(unsigned long long*)&xv[i].x, wlo);
                    ffma2(acc2[i][j], *(unsigned long long*)&xv[i].z, whi);
                }
            }
        }
        __syncthreads();
    }

    #pragma unroll
    for (int i = 0; i < 4; i++) {
        float* orow = outp + (size_t)(ty + i * 16) * ldo + n0 + tx;
        #pragma unroll
        for (int j = 0; j < 4; j++) {
            float2 v = *(float2*)&acc2[i][j];
            orow[j * 32] = v.x + v.y;
        }
    }
}

// ---------------------------------------------------------------------------
// Phase A (block b, 512 threads), deep-unrolled for MLP.
// ---------------------------------------------------------------------------
static __device__ void phaseA(int b, int t,
                              const float* __restrict__ hcur,
                              const float* __restrict__ x,
                              const float* __restrict__ mem,
                              const float* __restrict__ Wk,
                              const float* __restrict__ bk,
                              const float* __restrict__ Wri,
                              const float* __restrict__ bri,
                              float* sm)
{
    float* hs    = sm;          // 1024
    float* ex    = sm + 1024;   // 1024
    float* kq    = sm + 2048;   // 64
    float* red   = sm + 2112;   // 512
    float* readv = sm + 2624;   // 64
    float* sred  = sm + 2688;   // 32

    const int tid  = threadIdx.x;
    const int warp = tid >> 5;
    const int lane = tid & 31;

    hs[tid]       = hcur[b * HH + tid];
    hs[tid + 512] = hcur[b * HH + tid + 512];
    __syncthreads();

    #pragma unroll
    for (int mi = 0; mi < 4; mi++) {
        int m = warp * 4 + mi;
        const float* wrow = Wk + (size_t)m * HH;
        float s = 0.f;
        #pragma unroll 8
        for (int k = lane; k < HH; k += 32) s += hs[k] * wrow[k];
        #pragma unroll
        for (int off = 16; off; off >>= 1) s += __shfl_down_sync(0xffffffffu, s, off);
        if (lane == 0) kq[m] = s + bk[m];
    }
    __syncthreads();

    float s0 = 0.f, s1 = 0.f;
    const float* mt = g_memT + tid;
    #pragma unroll 16
    for (int m = 0; m < MM; m++) {
        float kv = kq[m];
        const float* row = mt + m * PP;
        s0 += kv * row[0];
        s1 += kv * row[512];
    }
    float lmax = fmaxf(s0, s1);
    #pragma unroll
    for (int off = 16; off; off >>= 1)
        lmax = fmaxf(lmax, __shfl_xor_sync(0xffffffffu, lmax, off));
    if (lane == 0) sred[warp] = lmax;
    __syncthreads();
    float bmax = sred[0];
    #pragma unroll
    for (int w = 1; w < 16; w++) bmax = fmaxf(bmax, sred[w]);

    float e0 = expf(s0 - bmax), e1 = expf(s1 - bmax);
    ex[tid] = e0; ex[tid + 512] = e1;
    float lsum = e0 + e1;
    #pragma unroll
    for (int off = 16; off; off >>= 1)
        lsum += __shfl_xor_sync(0xffffffffu, lsum, off);
    if (lane == 0) sred[16 + warp] = lsum;
    __syncthreads();
    float bsum = 0.f;
    #pragma unroll
    for (int w = 0; w < 16; w++) bsum += sred[16 + w];

    {
        int m = tid & 63;
        int q = tid >> 6;
        const float* mp = mem + (size_t)(q * 128) * MM + m;
        const float* ep = ex + q * 128;
        float pr = 0.f;
        #pragma unroll 8
        for (int p = 0; p < 128; p++) pr += ep[p] * mp[(size_t)p * MM];
        red[q * 64 + m] = pr;
    }
    __syncthreads();
    if (tid < MM) {
        float s = 0.f;
        #pragma unroll
        for (int q = 0; q < 8; q++) s += red[q * 64 + tid];
        readv[tid] = s / bsum;
    }
    __syncthreads();

    {
        int i = tid;
        const float4* wr = (const float4*)(Wri + (size_t)i * MM);
        float s = bri[i];
        #pragma unroll
        for (int m4 = 0; m4 < 16; m4++) {
            float4 w = wr[m4];
            s += readv[m4 * 4 + 0] * w.x + readv[m4 * 4 + 1] * w.y
               + readv[m4 * 4 + 2] * w.z + readv[m4 * 4 + 3] * w.w;
        }
        g_xin[b * II + i] = x[((size_t)b * TT + t) * II + i] + fmaxf(s, 0.f);
    }
    __syncthreads();
}

// ---------------------------------------------------------------------------
// Persistent megakernel. Jobs are uniform 64x128xKc=128 GEMM partials.
//   gh: 192 jobs (24 coltiles x 8 ksplits)   gi: 96 (24 x 4)   out: 32 (4 x 8)
//   S1: phaseA [0..63] || 2 jobs each [64..147]: out(t-1) 0..31, gh 0..135
//   S2: 152 jobs: gh 136..191, gi 0..95  (1/block, blocks 0..3 take a 2nd)
//   S3: GRU [0..127] || out combine+store(t-1) [128..147]
// ---------------------------------------------------------------------------
__global__ void __launch_bounds__(NT, 1) ntm_persist(
    const float* __restrict__ x,    const float* __restrict__ mem,
    const float* __restrict__ Wk,   const float* __restrict__ bk,
    const float* __restrict__ Wri,  const float* __restrict__ bri,
    const float* __restrict__ Wih,  const float* __restrict__ Whh,
    const float* __restrict__ bih,  const float* __restrict__ bhh,
    const float* __restrict__ Wout, const float* __restrict__ bout,
    float* __restrict__ out)
{
    extern __shared__ __align__(16) float smf[];   // 52,224 B
    float* xs = smf;
    float* ws = smf + 64 * LDS_;

    const int bid = blockIdx.x;
    const int tid = threadIdx.x;
    const int gid = bid * NT + tid;

    for (int e = gid; e < BB * HH; e += NB * NT) g_h[0][e] = 0.f;
    for (int e = gid; e < PP * MM; e += NB * NT) {
        int p = e >> 6, m = e & 63;
        g_memT[m * PP + p] = mem[e];
    }
    gsync();

    for (int t = 0; t <= TT; t++) {
        const float* hcur = g_h[t & 1];

        // ---- S1 ----
        if (bid < 64) {
            if (t < TT) phaseA(bid, t, hcur, x, mem, Wk, bk, Wri, bri, smf);
        } else {
            int base = (bid - 64) * 2;
            #pragma unroll
            for (int u = 0; u < 2; u++) {
                int e = base + u;
                if (e < 32) {                       // out(t-1) job
                    if (t >= 1) {
                        int ct = e >> 3, ks = e & 7;
                        gemm128(hcur, HH, ks * 128, Wout, HH, ks * 128,
                                ct * 128, 128, g_cp[ks], OO, xs, ws);
                    }
                } else if (t < TT) {                // gh job 0..135
                    int j = e - 32;
                    int ct = j >> 3, ks = j & 7;
                    gemm128(hcur, HH, ks * 128, Whh, HH, ks * 128,
                            ct * 128, 128, g_gh[ks], G3, xs, ws);
                }
            }
        }
        gsync();

        // ---- S2 ----
        if (t < TT) {
            #pragma unroll
            for (int u = 0; u < 2; u++) {
                int e = bid + u * NB;
                if (e >= 152) break;
                if (e < 56) {                       // gh job 136..191
                    int j = 136 + e;
                    int ct = j >> 3, ks = j & 7;
                    gemm128(hcur, HH, ks * 128, Whh, HH, ks * 128,
                            ct * 128, 128, g_gh[ks], G3, xs, ws);
                } else {                            // gi job 0..95
                    int j = e - 56;
                    int ct = j >> 2, ks = j & 3;
                    gemm128(g_xin, II, ks * 128, Wih, II, ks * 128,
                            ct * 128, 128, g_gi[ks], G3, xs, ws);
                }
            }
        }
        gsync();

        // ---- S3 ----
        if (bid < 128) {
            if (t < TT) {
                float* hnew = g_h[(t + 1) & 1];
                int e = gid;                        // 0..65535 exactly
                int b = e >> 10, c = e & 1023;
                size_t o = (size_t)b * G3 + c;
                float ir = bih[c], iz = bih[1024 + c], inn = bih[2048 + c];
                #pragma unroll
                for (int q = 0; q < 4; q++) {
                    ir  += g_gi[q][o];
                    iz  += g_gi[q][o + 1024];
                    inn += g_gi[q][o + 2048];
                }
                float hr = bhh[c], hz = bhh[1024 + c], hn = bhh[2048 + c];
                #pragma unroll
                for (int q = 0; q < 8; q++) {
                    hr += g_gh[q][o];
                    hz += g_gh[q][o + 1024];
                    hn += g_gh[q][o + 2048];
                }
                float rg = 1.f / (1.f + expf(-(ir + hr)));
                float zg = 1.f / (1.f + expf(-(iz + hz)));
                float ng = tanhf(inn + rg * hn);
                hnew[e] = (1.f - zg) * ng + zg * hcur[e];
            }
        } else if (t >= 1) {
            for (int e = (bid - 128) * NT + tid; e < BB * OO; e += 20 * NT) {
                int b = e >> 9, oc = e & (OO - 1);
                float s = bout[oc];
                #pragma unroll
                for (int q = 0; q < 8; q++) s += g_cp[q][e];
                out[((size_t)b * TT + (t - 1)) * OO + oc] = 1.f / (1.f + expf(-s));
            }
        }
        if (t == TT) break;
        gsync();
    }
}

extern "C" void kernel_launch(void* const* d_in, const int* in_sizes, int n_in,
                              void* d_out, int out_size)
{
    const float* x    = (const float*)d_in[0];
    const float* mem  = (const float*)d_in[1];
    const float* Wk   = (const float*)d_in[2];
    const float* bk   = (const float*)d_in[3];
    const float* Wri  = (const float*)d_in[4];
    const float* bri  = (const float*)d_in[5];
    const float* Wih  = (const float*)d_in[6];
    const float* Whh  = (const float*)d_in[7];
    const float* bih  = (const float*)d_in[8];
    const float* bhh  = (const float*)d_in[9];
    const float* Wout = (const float*)d_in[10];
    const float* bout = (const float*)d_in[11];

    static int once = 0;
    const int smem_bytes = (64 + 128) * LDS_ * 4;   // 52,224
    if (!once) {
        cudaFuncSetAttribute(ntm_persist,
                             cudaFuncAttributeMaxDynamicSharedMemorySize,
                             smem_bytes);
        once = 1;
    }

    ntm_persist<<<NB, NT, smem_bytes>>>(x, mem, Wk, bk, Wri, bri, Wih, Whh,
                                        bih, bhh, Wout, bout, (float*)d_out);
}

// round 13
// speedup vs baseline: 1.2009x; 1.2009x over previous
#include <cuda_runtime.h>
#include <math.h>
#include <stdint.h>

#define BB 64
#define TT 512
#define II 512
#define HH 1024
#define OO 512
#define MM 64
#define PP 1024
#define G3 3072
#define NB 148
#define NT 512
#define LDS_ 68
#define BUFW ((64 + 128) * LDS_)   // floats per stage buffer (13056)

__device__ __align__(16) float g_h[2][BB * HH];
__device__ __align__(16) float g_xin[BB * II];
__device__ __align__(16) float g_gi[2][BB * G3];   // gi K-splits (K=256)
__device__ __align__(16) float g_gh[4][BB * G3];   // gh K-splits (K=256)
__device__ __align__(16) float g_cp[4][BB * OO];   // out K-splits (K=256)
__device__ __align__(16) float g_memT[MM * PP];
__device__ volatile unsigned g_gen;
__device__ unsigned g_cnt;

static __device__ __forceinline__ void ffma2(unsigned long long& d,
                                             unsigned long long a,
                                             unsigned long long b)
{
    asm("fma.rn.f32x2 %0, %1, %2, %0;" : "+l"(d) : "l"(a), "l"(b));
}

__device__ __forceinline__ void gsync()
{
    __syncthreads();
    __threadfence();
    if (threadIdx.x == 0) {
        unsigned my = g_gen;
        if (atomicAdd(&g_cnt, 1u) == NB - 1u) {
            atomicExch(&g_cnt, 0u);
            __threadfence();
            g_gen = my + 1u;
        } else {
            while (g_gen == my) { __nanosleep(64); }
        }
    }
    __syncthreads();
    __threadfence();
}

// ---------------------------------------------------------------------------
// 64(batch) x 128(cols) x (nch*64) GEMM partial. 512 threads, 4x4/thread,
// FFMA2 inner loop. Ping-pong smem buffers: ONE __syncthreads per chunk;
// next chunk is staged into the other buffer while computing the current.
// ---------------------------------------------------------------------------
static __device__ __forceinline__ void gemm128(
    const float* __restrict__ X, int ldx, int xoff,
    const float* __restrict__ W, int ldw, int woff,
    int n0, int nch, float* __restrict__ outp, int ldo,
    float* __restrict__ smf)
{
    const int tid = threadIdx.x;
    const int ty  = tid & 15;        // rows ty + {0,16,32,48}
    const int tx  = tid >> 4;        // cols tx + {0,32,64,96}
    const int sr  = tid >> 4;        // staging row base
    const int sk  = (tid & 15) << 2; // staging k

    unsigned long long acc2[4][4];
    #pragma unroll
    for (int i = 0; i < 4; i++)
        #pragma unroll
        for (int j = 0; j < 4; j++) acc2[i][j] = 0ull;

    float4 ra[2], rb[4];

    // chunk 0 -> regs -> buf0
    #pragma unroll
    for (int q = 0; q < 2; q++) {
        int idx = tid + q * NT, r = idx >> 4, kk = (idx & 15) << 2;
        ra[q] = *(const float4*)(X + (size_t)r * ldx + xoff + kk);
    }
    #pragma unroll
    for (int q = 0; q < 4; q++) {
        int idx = tid + q * NT, r = idx >> 4, kk = (idx & 15) << 2;
        rb[q] = *(const float4*)(W + (size_t)(n0 + r) * ldw + woff + kk);
    }
    #pragma unroll
    for (int q = 0; q < 2; q++) {
        int idx = tid + q * NT, r = idx >> 4, kk = (idx & 15) << 2;
        *(float4*)(smf + r * LDS_ + kk) = ra[q];
    }
    #pragma unroll
    for (int q = 0; q < 4; q++) {
        int idx = tid + q * NT, r = idx >> 4, kk = (idx & 15) << 2;
        *(float4*)(smf + (64 + r) * LDS_ + kk) = rb[q];
    }
    // chunk 1 -> regs
    if (nch > 1) {
        #pragma unroll
        for (int q = 0; q < 2; q++) {
            int idx = tid + q * NT, r = idx >> 4, kk = (idx & 15) << 2;
            ra[q] = *(const float4*)(X + (size_t)r * ldx + xoff + 64 + kk);
        }
        #pragma unroll
        for (int q = 0; q < 4; q++) {
            int idx = tid + q * NT, r = idx >> 4, kk = (idx & 15) << 2;
            rb[q] = *(const float4*)(W + (size_t)(n0 + r) * ldw + woff + 64 + kk);
        }
    }

    for (int c = 0; c < nch; c++) {
        __syncthreads();                       // buf[c&1] ready for all

        float* nbuf = smf + ((c + 1) & 1) * BUFW;
        if (c + 1 < nch) {
            // store pre-loaded chunk c+1 into the other buffer
            #pragma unroll
            for (int q = 0; q < 2; q++) {
                int idx = tid + q * NT, r = idx >> 4, kk = (idx & 15) << 2;
                *(float4*)(nbuf + r * LDS_ + kk) = ra[q];
            }
            #pragma unroll
            for (int q = 0; q < 4; q++) {
                int idx = tid + q * NT, r = idx >> 4, kk = (idx & 15) << 2;
                *(float4*)(nbuf + (64 + r) * LDS_ + kk) = rb[q];
            }
            // issue global loads for chunk c+2
            if (c + 2 < nch) {
                int k0 = (c + 2) << 6;
                #pragma unroll
                for (int q = 0; q < 2; q++) {
                    int idx = tid + q * NT, r = idx >> 4, kk = (idx & 15) << 2;
                    ra[q] = *(const float4*)(X + (size_t)r * ldx + xoff + k0 + kk);
                }
                #pragma unroll
                for (int q = 0; q < 4; q++) {
                    int idx = tid + q * NT, r = idx >> 4, kk = (idx & 15) << 2;
                    rb[q] = *(const float4*)(W + (size_t)(n0 + r) * ldw + woff + k0 + kk);
                }
            }
        }

        const float* xs = smf + (c & 1) * BUFW;
        const float* ws = xs + 64 * LDS_;
        const float* x0 = xs + ty * LDS_;
        const float* w0 = ws + tx * LDS_;
        #pragma unroll
        for (int k4 = 0; k4 < 16; k4++) {
            float4 xv[4];
            #pragma unroll
            for (int i = 0; i < 4; i++)
                xv[i] = *(const float4*)(x0 + i * 16 * LDS_ + k4 * 4);
            #pragma unroll
            for (int j = 0; j < 4; j++) {
                float4 wv = *(const float4*)(w0 + j * 32 * LDS_ + k4 * 4);
                unsigned long long wlo = *(unsigned long long*)&wv.x;
                unsigned long long whi = *(unsigned long long*)&wv.z;
                #pragma unroll
                for (int i = 0; i < 4; i++) {
                    ffma2(acc2[i][j], *(unsigned long long*)&xv[i].x, wlo);
                    ffma2(acc2[i][j], *(unsigned long long*)&xv[i].z, whi);
                }
            }
        }
    }
    __syncthreads();                            // protect buffers for next job

    #pragma unroll
    for (int i = 0; i < 4; i++) {
        float* orow = outp + (size_t)(ty + i * 16) * ldo + n0 + tx;
        #pragma unroll
        for (int j = 0; j < 4; j++) {
            float2 v = *(float2*)&acc2[i][j];
            orow[j * 32] = v.x + v.y;
        }
    }
}

// ---------------------------------------------------------------------------
// Phase A (block b, 512 threads)
// ---------------------------------------------------------------------------
static __device__ void phaseA(int b, int t,
                              const float* __restrict__ hcur,
                              const float* __restrict__ x,
                              const float* __restrict__ mem,
                              const float* __restrict__ Wk,
                              const float* __restrict__ bk,
                              const float* __restrict__ Wri,
                              const float* __restrict__ bri,
                              float* sm)
{
    float* hs    = sm;          // 1024
    float* ex    = sm + 1024;   // 1024
    float* kq    = sm + 2048;   // 64
    float* red   = sm + 2112;   // 512
    float* readv = sm + 2624;   // 64
    float* sred  = sm + 2688;   // 32

    const int tid  = threadIdx.x;
    const int warp = tid >> 5;
    const int lane = tid & 31;

    hs[tid]       = hcur[b * HH + tid];
    hs[tid + 512] = hcur[b * HH + tid + 512];
    __syncthreads();

    #pragma unroll
    for (int mi = 0; mi < 4; mi++) {
        int m = warp * 4 + mi;
        const float* wrow = Wk + (size_t)m * HH;
        float s = 0.f;
        #pragma unroll 8
        for (int k = lane; k < HH; k += 32) s += hs[k] * wrow[k];
        #pragma unroll
        for (int off = 16; off; off >>= 1) s += __shfl_down_sync(0xffffffffu, s, off);
        if (lane == 0) kq[m] = s + bk[m];
    }
    __syncthreads();

    float s0 = 0.f, s1 = 0.f;
    const float* mt = g_memT + tid;
    #pragma unroll 16
    for (int m = 0; m < MM; m++) {
        float kv = kq[m];
        const float* row = mt + m * PP;
        s0 += kv * row[0];
        s1 += kv * row[512];
    }
    float lmax = fmaxf(s0, s1);
    #pragma unroll
    for (int off = 16; off; off >>= 1)
        lmax = fmaxf(lmax, __shfl_xor_sync(0xffffffffu, lmax, off));
    if (lane == 0) sred[warp] = lmax;
    __syncthreads();
    float bmax = sred[0];
    #pragma unroll
    for (int w = 1; w < 16; w++) bmax = fmaxf(bmax, sred[w]);

    float e0 = expf(s0 - bmax), e1 = expf(s1 - bmax);
    ex[tid] = e0; ex[tid + 512] = e1;
    float lsum = e0 + e1;
    #pragma unroll
    for (int off = 16; off; off >>= 1)
        lsum += __shfl_xor_sync(0xffffffffu, lsum, off);
    if (lane == 0) sred[16 + warp] = lsum;
    __syncthreads();
    float bsum = 0.f;
    #pragma unroll
    for (int w = 0; w < 16; w++) bsum += sred[16 + w];

    {
        int m = tid & 63;
        int q = tid >> 6;
        const float* mp = mem + (size_t)(q * 128) * MM + m;
        const float* ep = ex + q * 128;
        float pr = 0.f;
        #pragma unroll 8
        for (int p = 0; p < 128; p++) pr += ep[p] * mp[(size_t)p * MM];
        red[q * 64 + m] = pr;
    }
    __syncthreads();
    if (tid < MM) {
        float s = 0.f;
        #pragma unroll
        for (int q = 0; q < 8; q++) s += red[q * 64 + tid];
        readv[tid] = s / bsum;
    }
    __syncthreads();

    {
        int i = tid;
        const float4* wr = (const float4*)(Wri + (size_t)i * MM);
        float s = bri[i];
        #pragma unroll
        for (int m4 = 0; m4 < 16; m4++) {
            float4 w = wr[m4];
            s += readv[m4 * 4 + 0] * w.x + readv[m4 * 4 + 1] * w.y
               + readv[m4 * 4 + 2] * w.z + readv[m4 * 4 + 3] * w.w;
        }
        g_xin[b * II + i] = x[((size_t)b * TT + t) * II + i] + fmaxf(s, 0.f);
    }
    __syncthreads();
}

// ---------------------------------------------------------------------------
// Persistent megakernel. Uniform 4-chunk (Kc=256) GEMM jobs:
//   gh: 96 jobs (24 ct x 4 ks)  gi: 48 (24 x 2)  out: 16 (4 x 4)
//   S1: phaseA [0..63] || out(t-1) [64..79] || gh 0..67 [80..147]
//   S2: gh 68..95 [0..27] || gi 0..47 [28..75] || out combine(t-1) [76..79]
//   S3: GRU [0..127]
// ---------------------------------------------------------------------------
__global__ void __launch_bounds__(NT, 1) ntm_persist(
    const float* __restrict__ x,    const float* __restrict__ mem,
    const float* __restrict__ Wk,   const float* __restrict__ bk,
    const float* __restrict__ Wri,  const float* __restrict__ bri,
    const float* __restrict__ Wih,  const float* __restrict__ Whh,
    const float* __restrict__ bih,  const float* __restrict__ bhh,
    const float* __restrict__ Wout, const float* __restrict__ bout,
    float* __restrict__ out)
{
    extern __shared__ __align__(16) float smf[];   // 104,448 B
    const int bid = blockIdx.x;
    const int tid = threadIdx.x;
    const int gid = bid * NT + tid;

    for (int e = gid; e < BB * HH; e += NB * NT) g_h[0][e] = 0.f;
    for (int e = gid; e < PP * MM; e += NB * NT) {
        int p = e >> 6, m = e & 63;
        g_memT[m * PP + p] = mem[e];
    }
    gsync();

    for (int t = 0; t <= TT; t++) {
        const float* hcur = g_h[t & 1];

        // ---- S1 ----
        if (bid < 64) {
            if (t < TT) phaseA(bid, t, hcur, x, mem, Wk, bk, Wri, bri, smf);
        } else if (bid < 80) {
            if (t >= 1) {
                int j = bid - 64, ct = j >> 2, ks = j & 3;
                gemm128(hcur, HH, ks * 256, Wout, HH, ks * 256,
                        ct * 128, 4, g_cp[ks], OO, smf);
            }
        } else {
            if (t < TT) {
                int j = bid - 80;                 // gh job 0..67
                int ct = j >> 2, ks = j & 3;
                gemm128(hcur, HH, ks * 256, Whh, HH, ks * 256,
                        ct * 128, 4, g_gh[ks], G3, smf);
            }
        }
        gsync();

        // ---- S2 ----
        if (bid < 28) {
            if (t < TT) {
                int j = 68 + bid;                 // gh job 68..95
                int ct = j >> 2, ks = j & 3;
                gemm128(hcur, HH, ks * 256, Whh, HH, ks * 256,
                        ct * 128, 4, g_gh[ks], G3, smf);
            }
        } else if (bid < 76) {
            if (t < TT) {
                int j = bid - 28;                 // gi job 0..47
                int ct = j >> 1, ks = j & 1;
                gemm128(g_xin, II, ks * 256, Wih, II, ks * 256,
                        ct * 128, 4, g_gi[ks], G3, smf);
            }
        } else if (bid < 80) {
            if (t >= 1) {
                int idx = (bid - 76) * NT + tid;  // 0..2047
                for (int e = idx; e < BB * OO; e += 4 * NT) {
                    int b = e >> 9, oc = e & (OO - 1);
                    float s = bout[oc] + g_cp[0][e] + g_cp[1][e]
                            + g_cp[2][e] + g_cp[3][e];
                    out[((size_t)b * TT + (t - 1)) * OO + oc] =
                        1.f / (1.f + expf(-s));
                }
            }
        }
        if (t == TT) break;
        gsync();

        // ---- S3: GRU -> h(t+1) ----
        if (bid < 128) {
            float* hnew = g_h[(t + 1) & 1];
            int e = gid;                          // 0..65535 exactly
            int b = e >> 10, c = e & 1023;
            size_t o = (size_t)b * G3 + c;
            float ir  = g_gi[0][o]        + g_gi[1][o]        + bih[c];
            float iz  = g_gi[0][o + 1024] + g_gi[1][o + 1024] + bih[1024 + c];
            float inn = g_gi[0][o + 2048] + g_gi[1][o + 2048] + bih[2048 + c];
            float hr = bhh[c], hz = bhh[1024 + c], hn = bhh[2048 + c];
            #pragma unroll
            for (int q = 0; q < 4; q++) {
                hr += g_gh[q][o];
                hz += g_gh[q][o + 1024];
                hn += g_gh[q][o + 2048];
            }
            float rg = 1.f / (1.f + expf(-(ir + hr)));
            float zg = 1.f / (1.f + expf(-(iz + hz)));
            float ng = tanhf(inn + rg * hn);
            hnew[e] = (1.f - zg) * ng + zg * hcur[e];
        }
        gsync();
    }
}

extern "C" void kernel_launch(void* const* d_in, const int* in_sizes, int n_in,
                              void* d_out, int out_size)
{
    const float* x    = (const float*)d_in[0];
    const float* mem  = (const float*)d_in[1];
    const float* Wk   = (const float*)d_in[2];
    const float* bk   = (const float*)d_in[3];
    const float* Wri  = (const float*)d_in[4];
    const float* bri  = (const float*)d_in[5];
    const float* Wih  = (const float*)d_in[6];
    const float* Whh  = (const float*)d_in[7];
    const float* bih  = (const float*)d_in[8];
    const float* bhh  = (const float*)d_in[9];
    const float* Wout = (const float*)d_in[10];
    const float* bout = (const float*)d_in[11];

    static int once = 0;
    const int smem_bytes = 2 * BUFW * 4;   // 104,448
    if (!once) {
        cudaFuncSetAttribute(ntm_persist,
                             cudaFuncAttributeMaxDynamicSharedMemorySize,
                             smem_bytes);
        once = 1;
    }

    ntm_persist<<<NB, NT, smem_bytes>>>(x, mem, Wk, bk, Wri, bri, Wih, Whh,
                                        bih, bhh, Wout, bout, (float*)d_out);
}

// round 14
// speedup vs baseline: 1.8615x; 1.5501x over previous
#include <cuda_runtime.h>
#include <math.h>
#include <stdint.h>

#define BB 64
#define TT 512
#define II 512
#define HH 1024
#define OO 512
#define MM 64
#define PP 1024
#define G3 3072
#define NB 148
#define NT 512

// smem buffer geometry (bytes): Xh 8K | Xl 8K | Wh 16K | Wl 16K per buffer
#define XH_OFF 0
#define XL_OFF 8192
#define WH_OFF 16384
#define WL_OFF 32768
#define BUF_BYTES 49152

__device__ __align__(16) float g_h[2][BB * HH];
__device__ __align__(16) float g_xin[BB * II];
__device__ __align__(16) float g_gi[2][BB * G3];   // gi K-splits (K=256)
__device__ __align__(16) float g_gh[4][BB * G3];   // gh K-splits (K=256)
__device__ __align__(16) float g_cp[4][BB * OO];   // out K-splits (K=256)
__device__ __align__(16) float g_memT[MM * PP];
__device__ volatile unsigned g_gen;
__device__ unsigned g_cnt;

static __device__ __forceinline__ uint32_t smem_u32(const void* p)
{
    uint32_t a;
    asm("{ .reg .u64 t; cvta.to.shared.u64 t, %1; cvt.u32.u64 %0, t; }"
        : "=r"(a) : "l"(p));
    return a;
}

__device__ __forceinline__ void gsync()
{
    __syncthreads();
    __threadfence();
    if (threadIdx.x == 0) {
        unsigned my = g_gen;
        if (atomicAdd(&g_cnt, 1u) == NB - 1u) {
            atomicExch(&g_cnt, 0u);
            __threadfence();
            g_gen = my + 1u;
        } else {
            while (g_gen == my) { __nanosleep(64); }
        }
    }
    __syncthreads();
    __threadfence();
}

// pack two f32 into bf16x2 {lo, hi}
static __device__ __forceinline__ uint32_t pack2(float lo, float hi)
{
    uint32_t r;
    asm("cvt.rn.bf16x2.f32 %0, %1, %2;" : "=r"(r) : "f"(hi), "f"(lo));
    return r;
}

static __device__ __forceinline__ void ldsm4(uint32_t& r0, uint32_t& r1,
                                             uint32_t& r2, uint32_t& r3,
                                             uint32_t a)
{
    asm volatile("ldmatrix.sync.aligned.m8n8.x4.shared.b16 {%0,%1,%2,%3}, [%4];"
                 : "=r"(r0), "=r"(r1), "=r"(r2), "=r"(r3) : "r"(a));
}

static __device__ __forceinline__ void mma4(float* d, const uint32_t* a,
                                            uint32_t b0, uint32_t b1)
{
    asm volatile(
        "mma.sync.aligned.m16n8k16.row.col.f32.bf16.bf16.f32 "
        "{%0,%1,%2,%3}, {%4,%5,%6,%7}, {%8,%9}, {%0,%1,%2,%3};"
        : "+f"(d[0]), "+f"(d[1]), "+f"(d[2]), "+f"(d[3])
        : "r"(a[0]), "r"(a[1]), "r"(a[2]), "r"(a[3]), "r"(b0), "r"(b1));
}

// ---------------------------------------------------------------------------
// HMMA job: D[64 batch x 128 cols] partial = X[64 x Kc] * W[n0..n0+127, Kc]^T
// bf16 hi/lo split (3 terms). Kc = nch*64. 512 threads = 16 warps:
// warp w -> rows (w&3)*16..+15, cols (w>>2)*32..+31 (4 m16n8 tiles).
// ---------------------------------------------------------------------------
static __device__ void hjob(
    const float* __restrict__ X, int ldx, int xoff,
    const float* __restrict__ W, int ldw, int woff,
    int n0, int nch, float* __restrict__ outp, int ldo,
    uint32_t sb)
{
    const int tid = threadIdx.x;
    const int l   = tid & 31;
    const int wrp = tid >> 5;
    const int rg  = wrp & 3;
    const int cg  = wrp >> 2;

    float d[4][4];
    #pragma unroll
    for (int i = 0; i < 4; i++)
        d[i][0] = d[i][1] = d[i][2] = d[i][3] = 0.f;

    // ldmatrix lane geometry
    const int am    = l >> 3;
    const int alr   = l & 7;
    const int arow  = rg * 16 + ((am & 1) << 3) + alr;
    const uint32_t arow_off = (uint32_t)arow * 128u;
    const int ahalf = am >> 1;
    const int aswz  = arow & 7;
    const int brow0 = cg * 32 + ((am >> 1) << 3) + alr;  // pair p adds +16
    const int bhalf = am & 1;

    float4 vx[2], vw[4];

    // load chunk k0 into regs
    auto load_chunk = [&](int k0) {
        #pragma unroll
        for (int q = 0; q < 2; q++) {
            int idx = tid + q * NT, r = idx >> 4, f4 = idx & 15;
            vx[q] = *(const float4*)(X + (size_t)r * ldx + xoff + k0 + f4 * 4);
        }
        #pragma unroll
        for (int q = 0; q < 4; q++) {
            int idx = tid + q * NT, r = idx >> 4, f4 = idx & 15;
            vw[q] = *(const float4*)(W + (size_t)(n0 + r) * ldw + woff + k0 + f4 * 4);
        }
    };

    // convert + store regs into buffer bb (swizzled bf16 hi/lo tiles)
    auto store_chunk = [&](uint32_t bb) {
        #pragma unroll
        for (int q = 0; q < 2; q++) {
            int idx = tid + q * NT, r = idx >> 4, f4 = idx & 15;
            uint32_t sw = (uint32_t)((f4 * 8) ^ ((r & 7) << 4));
            float4 v = vx[q];
            uint32_t h01 = pack2(v.x, v.y);
            uint32_t h23 = pack2(v.z, v.w);
            float l0 = v.x - __uint_as_float(h01 << 16);
            float l1 = v.y - __uint_as_float(h01 & 0xFFFF0000u);
            float l2 = v.z - __uint_as_float(h23 << 16);
            float l3 = v.w - __uint_as_float(h23 & 0xFFFF0000u);
            uint32_t q01 = pack2(l0, l1);
            uint32_t q23 = pack2(l2, l3);
            uint32_t base = bb + (uint32_t)r * 128u + sw;
            asm volatile("st.shared.v2.u32 [%0], {%1,%2};"
                         :: "r"(base + XH_OFF), "r"(h01), "r"(h23));
            asm volatile("st.shared.v2.u32 [%0], {%1,%2};"
                         :: "r"(base + XL_OFF), "r"(q01), "r"(q23));
        }
        #pragma unroll
        for (int q = 0; q < 4; q++) {
            int idx = tid + q * NT, r = idx >> 4, f4 = idx & 15;
            uint32_t sw = (uint32_t)((f4 * 8) ^ ((r & 7) << 4));
            float4 v = vw[q];
            uint32_t h01 = pack2(v.x, v.y);
            uint32_t h23 = pack2(v.z, v.w);
            float l0 = v.x - __uint_as_float(h01 << 16);
            float l1 = v.y - __uint_as_float(h01 & 0xFFFF0000u);
            float l2 = v.z - __uint_as_float(h23 << 16);
            float l3 = v.w - __uint_as_float(h23 & 0xFFFF0000u);
            uint32_t q01 = pack2(l0, l1);
            uint32_t q23 = pack2(l2, l3);
            uint32_t base = bb + (uint32_t)r * 128u + sw;
            asm volatile("st.shared.v2.u32 [%0], {%1,%2};"
                         :: "r"(base + WH_OFF), "r"(h01), "r"(h23));
            asm volatile("st.shared.v2.u32 [%0], {%1,%2};"
                         :: "r"(base + WL_OFF), "r"(q01), "r"(q23));
        }
    };

    auto compute_chunk = [&](uint32_t bb) {
        #pragma unroll
        for (int s = 0; s < 4; s++) {
            uint32_t ao = (uint32_t)((s * 2 + ahalf) ^ aswz) << 4;
            uint32_t Ah[4], Al[4];
            ldsm4(Ah[0], Ah[1], Ah[2], Ah[3], bb + XH_OFF + arow_off + ao);
            ldsm4(Al[0], Al[1], Al[2], Al[3], bb + XL_OFF + arow_off + ao);
            uint32_t Bh[2][4], Bl[2][4];
            #pragma unroll
            for (int p = 0; p < 2; p++) {
                int brow = brow0 + p * 16;
                uint32_t bo = (uint32_t)brow * 128u
                            + ((uint32_t)((s * 2 + bhalf) ^ (brow & 7)) << 4);
                ldsm4(Bh[p][0], Bh[p][1], Bh[p][2], Bh[p][3], bb + WH_OFF + bo);
                ldsm4(Bl[p][0], Bl[p][1], Bl[p][2], Bl[p][3], bb + WL_OFF + bo);
            }
            #pragma unroll
            for (int nt = 0; nt < 4; nt++) {
                int p = nt >> 1, u = (nt & 1) << 1;
                mma4(d[nt], Ah, Bh[p][u], Bh[p][u + 1]);
                mma4(d[nt], Ah, Bl[p][u], Bl[p][u + 1]);
                mma4(d[nt], Al, Bh[p][u], Bh[p][u + 1]);
            }
        }
    };

    load_chunk(0);
    store_chunk(sb);                       // chunk 0 -> buf 0
    for (int c = 0; c < nch; c++) {
        if (c + 1 < nch) load_chunk((c + 1) * 64);
        __syncthreads();                   // buf[c&1] visible to all
        compute_chunk(sb + (uint32_t)(c & 1) * BUF_BYTES);
        if (c + 1 < nch) store_chunk(sb + (uint32_t)((c + 1) & 1) * BUF_BYTES);
    }

    // D writeout: d0,d1 -> row rg*16 + l/4, cols +{0,1}; d2,d3 -> row +8
    #pragma unroll
    for (int nt = 0; nt < 4; nt++) {
        int col  = n0 + cg * 32 + nt * 8 + (l & 3) * 2;
        int row0 = rg * 16 + (l >> 2);
        *(float2*)(outp + (size_t)row0 * ldo + col) = make_float2(d[nt][0], d[nt][1]);
        *(float2*)(outp + (size_t)(row0 + 8) * ldo + col) = make_float2(d[nt][2], d[nt][3]);
    }
}

// ---------------------------------------------------------------------------
// Phase A (block b, 512 threads) — fp32, unchanged
// ---------------------------------------------------------------------------
static __device__ void phaseA(int b, int t,
                              const float* __restrict__ hcur,
                              const float* __restrict__ x,
                              const float* __restrict__ mem,
                              const float* __restrict__ Wk,
                              const float* __restrict__ bk,
                              const float* __restrict__ Wri,
                              const float* __restrict__ bri,
                              float* sm)
{
    float* hs    = sm;          // 1024
    float* ex    = sm + 1024;   // 1024
    float* kq    = sm + 2048;   // 64
    float* red   = sm + 2112;   // 512
    float* readv = sm + 2624;   // 64
    float* sred  = sm + 2688;   // 32

    const int tid  = threadIdx.x;
    const int warp = tid >> 5;
    const int lane = tid & 31;

    hs[tid]       = hcur[b * HH + tid];
    hs[tid + 512] = hcur[b * HH + tid + 512];
    __syncthreads();

    #pragma unroll
    for (int mi = 0; mi < 4; mi++) {
        int m = warp * 4 + mi;
        const float* wrow = Wk + (size_t)m * HH;
        float s = 0.f;
        #pragma unroll 8
        for (int k = lane; k < HH; k += 32) s += hs[k] * wrow[k];
        #pragma unroll
        for (int off = 16; off; off >>= 1) s += __shfl_down_sync(0xffffffffu, s, off);
        if (lane == 0) kq[m] = s + bk[m];
    }
    __syncthreads();

    float s0 = 0.f, s1 = 0.f;
    const float* mt = g_memT + tid;
    #pragma unroll 16
    for (int m = 0; m < MM; m++) {
        float kv = kq[m];
        const float* row = mt + m * PP;
        s0 += kv * row[0];
        s1 += kv * row[512];
    }
    float lmax = fmaxf(s0, s1);
    #pragma unroll
    for (int off = 16; off; off >>= 1)
        lmax = fmaxf(lmax, __shfl_xor_sync(0xffffffffu, lmax, off));
    if (lane == 0) sred[warp] = lmax;
    __syncthreads();
    float bmax = sred[0];
    #pragma unroll
    for (int w = 1; w < 16; w++) bmax = fmaxf(bmax, sred[w]);

    float e0 = expf(s0 - bmax), e1 = expf(s1 - bmax);
    ex[tid] = e0; ex[tid + 512] = e1;
    float lsum = e0 + e1;
    #pragma unroll
    for (int off = 16; off; off >>= 1)
        lsum += __shfl_xor_sync(0xffffffffu, lsum, off);
    if (lane == 0) sred[16 + warp] = lsum;
    __syncthreads();
    float bsum = 0.f;
    #pragma unroll
    for (int w = 0; w < 16; w++) bsum += sred[16 + w];

    {
        int m = tid & 63;
        int q = tid >> 6;
        const float* mp = mem + (size_t)(q * 128) * MM + m;
        const float* ep = ex + q * 128;
        float pr = 0.f;
        #pragma unroll 8
        for (int p = 0; p < 128; p++) pr += ep[p] * mp[(size_t)p * MM];
        red[q * 64 + m] = pr;
    }
    __syncthreads();
    if (tid < MM) {
        float s = 0.f;
        #pragma unroll
        for (int q = 0; q < 8; q++) s += red[q * 64 + tid];
        readv[tid] = s / bsum;
    }
    __syncthreads();

    {
        int i = tid;
        const float4* wr = (const float4*)(Wri + (size_t)i * MM);
        float s = bri[i];
        #pragma unroll
        for (int m4 = 0; m4 < 16; m4++) {
            float4 w = wr[m4];
            s += readv[m4 * 4 + 0] * w.x + readv[m4 * 4 + 1] * w.y
               + readv[m4 * 4 + 2] * w.z + readv[m4 * 4 + 3] * w.w;
        }
        g_xin[b * II + i] = x[((size_t)b * TT + t) * II + i] + fmaxf(s, 0.f);
    }
    __syncthreads();
}

// ---------------------------------------------------------------------------
// Persistent megakernel. Uniform Kc=256 HMMA jobs:
//   gh: 96 (24ct x 4ks)   gi: 48 (24ct x 2ks)   out: 16 (4ct x 4ks)
//   S1: phaseA [0..63] || out(t-1) [64..79] || gh 0..67 [80..147]
//   S2: gh 68..95 [0..27] || gi [28..75] || out combine(t-1) [76..79]
//   S3: GRU [0..127]
// ---------------------------------------------------------------------------
__global__ void __launch_bounds__(NT, 1) ntm_persist(
    const float* __restrict__ x,    const float* __restrict__ mem,
    const float* __restrict__ Wk,   const float* __restrict__ bk,
    const float* __restrict__ Wri,  const float* __restrict__ bri,
    const float* __restrict__ Wih,  const float* __restrict__ Whh,
    const float* __restrict__ bih,  const float* __restrict__ bhh,
    const float* __restrict__ Wout, const float* __restrict__ bout,
    float* __restrict__ out)
{
    extern __shared__ __align__(16) char dsm[];     // 98,304 B (2 buffers)
    __shared__ float sA[2720];                      // phaseA scratch
    const uint32_t sb = smem_u32(dsm);

    const int bid = blockIdx.x;
    const int tid = threadIdx.x;
    const int gid = bid * NT + tid;

    for (int e = gid; e < BB * HH; e += NB * NT) g_h[0][e] = 0.f;
    for (int e = gid; e < PP * MM; e += NB * NT) {
        int p = e >> 6, m = e & 63;
        g_memT[m * PP + p] = mem[e];
    }
    gsync();

    for (int t = 0; t <= TT; t++) {
        const float* hcur = g_h[t & 1];

        // ---- S1 ----
        if (bid < 64) {
            if (t < TT) phaseA(bid, t, hcur, x, mem, Wk, bk, Wri, bri, sA);
        } else if (bid < 80) {
            if (t >= 1) {
                int j = bid - 64, ct = j >> 2, ks = j & 3;
                hjob(hcur, HH, ks * 256, Wout, HH, ks * 256,
                     ct * 128, 4, g_cp[ks], OO, sb);
            }
        } else {
            if (t < TT) {
                int j = bid - 80;                 // gh job 0..67
                int ct = j >> 2, ks = j & 3;
                hjob(hcur, HH, ks * 256, Whh, HH, ks * 256,
                     ct * 128, 4, g_gh[ks], G3, sb);
            }
        }
        gsync();

        // ---- S2 ----
        if (bid < 28) {
            if (t < TT) {
                int j = 68 + bid;                 // gh job 68..95
                int ct = j >> 2, ks = j & 3;
                hjob(hcur, HH, ks * 256, Whh, HH, ks * 256,
                     ct * 128, 4, g_gh[ks], G3, sb);
            }
        } else if (bid < 76) {
            if (t < TT) {
                int j = bid - 28;                 // gi job 0..47
                int ct = j >> 1, ks = j & 1;
                hjob(g_xin, II, ks * 256, Wih, II, ks * 256,
                     ct * 128, 4, g_gi[ks], G3, sb);
            }
        } else if (bid < 80) {
            if (t >= 1) {
                int idx = (bid - 76) * NT + tid;  // 0..2047
                for (int e = idx; e < BB * OO; e += 4 * NT) {
                    int b = e >> 9, oc = e & (OO - 1);
                    float s = bout[oc] + g_cp[0][e] + g_cp[1][e]
                            + g_cp[2][e] + g_cp[3][e];
                    out[((size_t)b * TT + (t - 1)) * OO + oc] =
                        1.f / (1.f + expf(-s));
                }
            }
        }
        if (t == TT) break;
        gsync();

        // ---- S3: GRU -> h(t+1) ----
        if (bid < 128) {
            float* hnew = g_h[(t + 1) & 1];
            int e = gid;                          // 0..65535 exactly
            int b = e >> 10, c = e & 1023;
            size_t o = (size_t)b * G3 + c;
            float ir  = g_gi[0][o]        + g_gi[1][o]        + bih[c];
            float iz  = g_gi[0][o + 1024] + g_gi[1][o + 1024] + bih[1024 + c];
            float inn = g_gi[0][o + 2048] + g_gi[1][o + 2048] + bih[2048 + c];
            float hr = bhh[c], hz = bhh[1024 + c], hn = bhh[2048 + c];
            #pragma unroll
            for (int q = 0; q < 4; q++) {
                hr += g_gh[q][o];
                hz += g_gh[q][o + 1024];
                hn += g_gh[q][o + 2048];
            }
            float rg = 1.f / (1.f + expf(-(ir + hr)));
            float zg = 1.f / (1.f + expf(-(iz + hz)));
            float ng = tanhf(inn + rg * hn);
            hnew[e] = (1.f - zg) * ng + zg * hcur[e];
        }
        gsync();
    }
}

extern "C" void kernel_launch(void* const* d_in, const int* in_sizes, int n_in,
                              void* d_out, int out_size)
{
    const float* x    = (const float*)d_in[0];
    const float* mem  = (const float*)d_in[1];
    const float* Wk   = (const float*)d_in[2];
    const float* bk   = (const float*)d_in[3];
    const float* Wri  = (const float*)d_in[4];
    const float* bri  = (const float*)d_in[5];
    const float* Wih  = (const float*)d_in[6];
    const float* Whh  = (const float*)d_in[7];
    const float* bih  = (const float*)d_in[8];
    const float* bhh  = (const float*)d_in[9];
    const float* Wout = (const float*)d_in[10];
    const float* bout = (const float*)d_in[11];

    static int once = 0;
    const int smem_bytes = 2 * BUF_BYTES;   // 98,304
    if (!once) {
        cudaFuncSetAttribute(ntm_persist,
                             cudaFuncAttributeMaxDynamicSharedMemorySize,
                             smem_bytes);
        once = 1;
    }

    ntm_persist<<<NB, NT, smem_bytes>>>(x, mem, Wk, bk, Wri, bri, Wih, Whh,
                                        bih, bhh, Wout, bout, (float*)d_out);
}

// round 15
// speedup vs baseline: 1.9977x; 1.0732x over previous
#include <cuda_runtime.h>
#include <math.h>
#include <stdint.h>

#define BB 64
#define TT 512
#define II 512
#define HH 1024
#define OO 512
#define MM 64
#define PP 1024
#define G3 3072
#define NB 148
#define NT 512

#define STAGE_BYTES 49152u        // X 16KB + W 32KB
// stage layout: [Xh 8K][Xl 8K][Wh 16K][Wl 16K]

__device__ __align__(16) float g_h[2][BB * HH];
__device__ __align__(16) float g_gi[2][BB * G3];    // gi K-splits (K=256)
__device__ __align__(16) float g_gh[4][BB * G3];    // gh K-splits (K=256)
__device__ __align__(16) float g_cp[4][BB * OO];    // out K-splits (K=256)
__device__ __align__(16) float g_memT[MM * PP];
// pre-converted bf16 hi/lo, pre-swizzled, smem-image layout
// W blocks: [0,192) Wih (24ct x 8kc), [192,576) Whh (24ct x 16kc),
//           [576,640) Wout (4ct x 16kc); each block 8192 words (hi 4096, lo 4096)
__device__ __align__(16) uint32_t g_Wpre[640 * 8192];      // 20 MB
__device__ __align__(16) uint32_t g_hpre[2][16 * 4096];    // h image, 16 kc blocks
__device__ __align__(16) uint32_t g_xpre[8 * 4096];        // xin image, 8 kc blocks
__device__ volatile unsigned g_gen;
__device__ unsigned g_cnt;

static __device__ __forceinline__ uint32_t smem_u32(const void* p)
{
    uint32_t a;
    asm("{ .reg .u64 t; cvta.to.shared.u64 t, %1; cvt.u32.u64 %0, t; }"
        : "=r"(a) : "l"(p));
    return a;
}

static __device__ __forceinline__ void cp16(uint32_t dst, const void* src)
{
    asm volatile("cp.async.cg.shared.global [%0], [%1], 16;"
                 :: "r"(dst), "l"(src));
}

__device__ __forceinline__ void gsync()
{
    __syncthreads();
    __threadfence();
    if (threadIdx.x == 0) {
        unsigned my = g_gen;
        if (atomicAdd(&g_cnt, 1u) == NB - 1u) {
            atomicExch(&g_cnt, 0u);
            __threadfence();
            g_gen = my + 1u;
        } else {
            while (g_gen == my) { __nanosleep(64); }
        }
    }
    __syncthreads();
    __threadfence();
}

static __device__ __forceinline__ uint32_t pack2(float lo, float hi)
{
    uint32_t r;
    asm("cvt.rn.bf16x2.f32 %0, %1, %2;" : "=r"(r) : "f"(hi), "f"(lo));
    return r;
}

static __device__ __forceinline__ void ldsm4(uint32_t& r0, uint32_t& r1,
                                             uint32_t& r2, uint32_t& r3,
                                             uint32_t a)
{
    asm volatile("ldmatrix.sync.aligned.m8n8.x4.shared.b16 {%0,%1,%2,%3}, [%4];"
                 : "=r"(r0), "=r"(r1), "=r"(r2), "=r"(r3) : "r"(a));
}

static __device__ __forceinline__ void mma4(float* d, const uint32_t* a,
                                            uint32_t b0, uint32_t b1)
{
    asm volatile(
        "mma.sync.aligned.m16n8k16.row.col.f32.bf16.bf16.f32 "
        "{%0,%1,%2,%3}, {%4,%5,%6,%7}, {%8,%9}, {%0,%1,%2,%3};"
        : "+f"(d[0]), "+f"(d[1]), "+f"(d[2]), "+f"(d[3])
        : "r"(a[0]), "r"(a[1]), "r"(a[2]), "r"(a[3]), "r"(b0), "r"(b1));
}

// ---------------------------------------------------------------------------
// HMMA job: D[64 x 128] partial from pre-packed bf16 images.
// preX: chunk stride 4096 words; preW: chunk stride 8192 words. nch chunks.
// 3-stage cp.async pipeline, one __syncthreads per chunk.
// ---------------------------------------------------------------------------
static __device__ void hjob(const uint32_t* __restrict__ preX,
                            const uint32_t* __restrict__ preW,
                            int nch, float* __restrict__ outp, int ldo,
                            int n0, uint32_t sb)
{
    const int tid = threadIdx.x;
    const int l   = tid & 31;
    const int wrp = tid >> 5;
    const int rg  = wrp & 3;
    const int cg  = wrp >> 2;

    float d[4][4];
    #pragma unroll
    for (int i = 0; i < 4; i++)
        d[i][0] = d[i][1] = d[i][2] = d[i][3] = 0.f;

    const int am    = l >> 3;
    const int alr   = l & 7;
    const int arow  = rg * 16 + ((am & 1) << 3) + alr;
    const uint32_t arow_off = (uint32_t)arow * 128u;
    const int ahalf = am >> 1;
    const int aswz  = arow & 7;
    const int brow0 = cg * 32 + ((am >> 1) << 3) + alr;
    const int bhalf = am & 1;

    auto issue = [&](int c) {
        if (c >= nch) return;
        uint32_t st = sb + (uint32_t)(c % 3) * STAGE_BYTES;
        const uint32_t* px = preX + (size_t)c * 4096;
        const uint32_t* pw = preW + (size_t)c * 8192;
        cp16(st + (uint32_t)tid * 16u, px + tid * 4);
        cp16(st + 8192u + (uint32_t)tid * 16u, px + 2048 + tid * 4);
        #pragma unroll
        for (int q = 0; q < 4; q++)
            cp16(st + 16384u + (uint32_t)(tid + q * 512) * 16u,
                 pw + (tid + q * 512) * 4);
        asm volatile("cp.async.commit_group;" ::: "memory");
    };

    issue(0);
    issue(1);

    for (int c = 0; c < nch; c++) {
        if (c + 1 < nch)
            asm volatile("cp.async.wait_group 1;" ::: "memory");
        else
            asm volatile("cp.async.wait_group 0;" ::: "memory");
        __syncthreads();

        uint32_t st = sb + (uint32_t)(c % 3) * STAGE_BYTES;
        #pragma unroll
        for (int s = 0; s < 4; s++) {
            uint32_t ao = (uint32_t)((s * 2 + ahalf) ^ aswz) << 4;
            uint32_t Ah[4], Al[4];
            ldsm4(Ah[0], Ah[1], Ah[2], Ah[3], st + arow_off + ao);
            ldsm4(Al[0], Al[1], Al[2], Al[3], st + 8192u + arow_off + ao);
            uint32_t Bh[2][4], Bl[2][4];
            #pragma unroll
            for (int p = 0; p < 2; p++) {
                int brow = brow0 + p * 16;
                uint32_t bo = (uint32_t)brow * 128u
                            + ((uint32_t)((s * 2 + bhalf) ^ (brow & 7)) << 4);
                ldsm4(Bh[p][0], Bh[p][1], Bh[p][2], Bh[p][3], st + 16384u + bo);
                ldsm4(Bl[p][0], Bl[p][1], Bl[p][2], Bl[p][3], st + 32768u + bo);
            }
            #pragma unroll
            for (int nt = 0; nt < 4; nt++) {
                int p = nt >> 1, u = (nt & 1) << 1;
                mma4(d[nt], Ah, Bh[p][u], Bh[p][u + 1]);
                mma4(d[nt], Ah, Bl[p][u], Bl[p][u + 1]);
                mma4(d[nt], Al, Bh[p][u], Bh[p][u + 1]);
            }
        }

        issue(c + 2);
    }

    #pragma unroll
    for (int nt = 0; nt < 4; nt++) {
        int col  = n0 + cg * 32 + nt * 8 + (l & 3) * 2;
        int row0 = rg * 16 + (l >> 2);
        *(float2*)(outp + (size_t)row0 * ldo + col) = make_float2(d[nt][0], d[nt][1]);
        *(float2*)(outp + (size_t)(row0 + 8) * ldo + col) = make_float2(d[nt][2], d[nt][3]);
    }
}

// ---------------------------------------------------------------------------
// Phase A (block b, 512 threads): content read + softmax + relu -> xin bf16 image
// ---------------------------------------------------------------------------
static __device__ void phaseA(int b, int t,
                              const float* __restrict__ hcur,
                              const float* __restrict__ x,
                              const float* __restrict__ mem,
                              const float* __restrict__ Wk,
                              const float* __restrict__ bk,
                              const float* __restrict__ Wri,
                              const float* __restrict__ bri,
                              float* sm)
{
    float* hs    = sm;          // 1024
    float* ex    = sm + 1024;   // 1024
    float* kq    = sm + 2048;   // 64
    float* red   = sm + 2112;   // 512
    float* readv = sm + 2624;   // 64
    float* sred  = sm + 2688;   // 32

    const int tid  = threadIdx.x;
    const int warp = tid >> 5;
    const int lane = tid & 31;

    hs[tid]       = hcur[b * HH + tid];
    hs[tid + 512] = hcur[b * HH + tid + 512];
    __syncthreads();

    #pragma unroll
    for (int mi = 0; mi < 4; mi++) {
        int m = warp * 4 + mi;
        const float* wrow = Wk + (size_t)m * HH;
        float s = 0.f;
        #pragma unroll 8
        for (int k = lane; k < HH; k += 32) s += hs[k] * wrow[k];
        #pragma unroll
        for (int off = 16; off; off >>= 1) s += __shfl_down_sync(0xffffffffu, s, off);
        if (lane == 0) kq[m] = s + bk[m];
    }
    __syncthreads();

    float s0 = 0.f, s1 = 0.f;
    const float* mt = g_memT + tid;
    #pragma unroll 16
    for (int m = 0; m < MM; m++) {
        float kv = kq[m];
        const float* row = mt + m * PP;
        s0 += kv * row[0];
        s1 += kv * row[512];
    }
    float lmax = fmaxf(s0, s1);
    #pragma unroll
    for (int off = 16; off; off >>= 1)
        lmax = fmaxf(lmax, __shfl_xor_sync(0xffffffffu, lmax, off));
    if (lane == 0) sred[warp] = lmax;
    __syncthreads();
    float bmax = sred[0];
    #pragma unroll
    for (int w = 1; w < 16; w++) bmax = fmaxf(bmax, sred[w]);

    float e0 = expf(s0 - bmax), e1 = expf(s1 - bmax);
    ex[tid] = e0; ex[tid + 512] = e1;
    float lsum = e0 + e1;
    #pragma unroll
    for (int off = 16; off; off >>= 1)
        lsum += __shfl_xor_sync(0xffffffffu, lsum, off);
    if (lane == 0) sred[16 + warp] = lsum;
    __syncthreads();
    float bsum = 0.f;
    #pragma unroll
    for (int w = 0; w < 16; w++) bsum += sred[16 + w];

    {
        int m = tid & 63;
        int q = tid >> 6;
        const float* mp = mem + (size_t)(q * 128) * MM + m;
        const float* ep = ex + q * 128;
        float pr = 0.f;
        #pragma unroll 8
        for (int p = 0; p < 128; p++) pr += ep[p] * mp[(size_t)p * MM];
        red[q * 64 + m] = pr;
    }
    __syncthreads();
    if (tid < MM) {
        float s = 0.f;
        #pragma unroll
        for (int q = 0; q < 8; q++) s += red[q * 64 + tid];
        readv[tid] = s / bsum;
    }
    __syncthreads();

    {
        int i = tid;
        const float4* wr = (const float4*)(Wri + (size_t)i * MM);
        float s = bri[i];
        #pragma unroll
        for (int m4 = 0; m4 < 16; m4++) {
            float4 w = wr[m4];
            s += readv[m4 * 4 + 0] * w.x + readv[m4 * 4 + 1] * w.y
               + readv[m4 * 4 + 2] * w.z + readv[m4 * 4 + 3] * w.w;
        }
        float v = x[((size_t)b * TT + t) * II + i] + fmaxf(s, 0.f);
        float vn = __shfl_down_sync(0xffffffffu, v, 1);
        if ((i & 1) == 0) {
            uint32_t hi = pack2(v, vn);
            float r0 = v  - __uint_as_float(hi << 16);
            float r1 = vn - __uint_as_float(hi & 0xFFFF0000u);
            uint32_t lo = pack2(r0, r1);
            int kc = i >> 6, f2 = (i & 63) >> 1;
            int word = kc * 4096 + b * 32 + (f2 ^ ((b & 7) << 2));
            g_xpre[word]        = hi;
            g_xpre[word + 2048] = lo;
        }
    }
    __syncthreads();
}

// ---------------------------------------------------------------------------
// Persistent megakernel (schedule identical to R14)
// ---------------------------------------------------------------------------
__global__ void __launch_bounds__(NT, 1) ntm_persist(
    const float* __restrict__ x,    const float* __restrict__ mem,
    const float* __restrict__ Wk,   const float* __restrict__ bk,
    const float* __restrict__ Wri,  const float* __restrict__ bri,
    const float* __restrict__ Wih,  const float* __restrict__ Whh,
    const float* __restrict__ bih,  const float* __restrict__ bhh,
    const float* __restrict__ Wout, const float* __restrict__ bout,
    float* __restrict__ out)
{
    extern __shared__ __align__(16) char dsm[];     // 3 stages = 147,456 B
    __shared__ float sA[2720];
    const uint32_t sb = smem_u32(dsm);

    const int bid = blockIdx.x;
    const int tid = threadIdx.x;
    const int gid = bid * NT + tid;

    // ---- one-time init ----
    for (int e = gid; e < BB * HH; e += NB * NT) g_h[0][e] = 0.f;
    for (int e = gid; e < 16 * 4096; e += NB * NT) g_hpre[0][e] = 0u;
    for (int e = gid; e < PP * MM; e += NB * NT) {
        int p = e >> 6, m = e & 63;
        g_memT[m * PP + p] = mem[e];
    }
    // weight pre-conversion: 640 chunk-blocks, smem-image layout
    for (int w = gid; w < 640 * 4096; w += NB * NT) {
        int blk = w >> 12, within = w & 4095;
        int r = within >> 5, sw = within & 31;
        int f2 = sw ^ ((r & 7) << 2);
        const float* src; int ldw, row, k;
        if (blk < 192) {
            int ct = blk >> 3, kc = blk & 7;
            src = Wih; ldw = II; row = ct * 128 + r; k = kc * 64 + f2 * 2;
        } else if (blk < 576) {
            int b2 = blk - 192, ct = b2 >> 4, kc = b2 & 15;
            src = Whh; ldw = HH; row = ct * 128 + r; k = kc * 64 + f2 * 2;
        } else {
            int b3 = blk - 576, ct = b3 >> 4, kc = b3 & 15;
            src = Wout; ldw = HH; row = ct * 128 + r; k = kc * 64 + f2 * 2;
        }
        float v0 = src[(size_t)row * ldw + k];
        float v1 = src[(size_t)row * ldw + k + 1];
        uint32_t hi = pack2(v0, v1);
        float r0 = v0 - __uint_as_float(hi << 16);
        float r1 = v1 - __uint_as_float(hi & 0xFFFF0000u);
        uint32_t lo = pack2(r0, r1);
        g_Wpre[(size_t)blk * 8192 + within]        = hi;
        g_Wpre[(size_t)blk * 8192 + 4096 + within] = lo;
    }
    gsync();

    for (int t = 0; t <= TT; t++) {
        const float* hcur = g_h[t & 1];
        const uint32_t* hpre = g_hpre[t & 1];

        // ---- S1: phaseA [0..63] || out(t-1) [64..79] || gh 0..67 [80..147]
        if (bid < 64) {
            if (t < TT) phaseA(bid, t, hcur, x, mem, Wk, bk, Wri, bri, sA);
        } else if (bid < 80) {
            if (t >= 1) {
                int j = bid - 64, ct = j >> 2, ks = j & 3;
                hjob(hpre + ks * 4 * 4096,
                     g_Wpre + (size_t)(576 + ct * 16 + ks * 4) * 8192,
                     4, g_cp[ks], OO, ct * 128, sb);
            }
        } else {
            if (t < TT) {
                int j = bid - 80, ct = j >> 2, ks = j & 3;
                hjob(hpre + ks * 4 * 4096,
                     g_Wpre + (size_t)(192 + ct * 16 + ks * 4) * 8192,
                     4, g_gh[ks], G3, ct * 128, sb);
            }
        }
        gsync();

        // ---- S2: gh 68..95 [0..27] || gi [28..75] || out combine [76..79]
        if (bid < 28) {
            if (t < TT) {
                int j = 68 + bid, ct = j >> 2, ks = j & 3;
                hjob(hpre + ks * 4 * 4096,
                     g_Wpre + (size_t)(192 + ct * 16 + ks * 4) * 8192,
                     4, g_gh[ks], G3, ct * 128, sb);
            }
        } else if (bid < 76) {
            if (t < TT) {
                int j = bid - 28, ct = j >> 1, ks = j & 1;
                hjob(g_xpre + ks * 4 * 4096,
                     g_Wpre + (size_t)(ct * 8 + ks * 4) * 8192,
                     4, g_gi[ks], G3, ct * 128, sb);
            }
        } else if (bid < 80) {
            if (t >= 1) {
                int idx = (bid - 76) * NT + tid;
                for (int e = idx; e < BB * OO; e += 4 * NT) {
                    int b = e >> 9, oc = e & (OO - 1);
                    float s = bout[oc] + g_cp[0][e] + g_cp[1][e]
                            + g_cp[2][e] + g_cp[3][e];
                    out[((size_t)b * TT + (t - 1)) * OO + oc] =
                        1.f / (1.f + expf(-s));
                }
            }
        }
        if (t == TT) break;
        gsync();

        // ---- S3: GRU -> h(t+1) f32 + bf16 image ----
        if (bid < 128) {
            float* hnew = g_h[(t + 1) & 1];
            uint32_t* hp = g_hpre[(t + 1) & 1];
            int e = gid;                          // 0..65535
            int b = e >> 10, c = e & 1023;
            size_t o = (size_t)b * G3 + c;
            float ir  = g_gi[0][o]        + g_gi[1][o]        + bih[c];
            float iz  = g_gi[0][o + 1024] + g_gi[1][o + 1024] + bih[1024 + c];
            float inn = g_gi[0][o + 2048] + g_gi[1][o + 2048] + bih[2048 + c];
            float hr = bhh[c], hz = bhh[1024 + c], hn = bhh[2048 + c];
            #pragma unroll
            for (int q = 0; q < 4; q++) {
                hr += g_gh[q][o];
                hz += g_gh[q][o + 1024];
                hn += g_gh[q][o + 2048];
            }
            float rg = 1.f / (1.f + expf(-(ir + hr)));
            float zg = 1.f / (1.f + expf(-(iz + hz)));
            float ng = tanhf(inn + rg * hn);
            float hv = (1.f - zg) * ng + zg * hcur[e];
            hnew[e] = hv;
            float vn = __shfl_down_sync(0xffffffffu, hv, 1);
            if ((e & 1) == 0) {
                uint32_t hi = pack2(hv, vn);
                float r0 = hv - __uint_as_float(hi << 16);
                float r1 = vn - __uint_as_float(hi & 0xFFFF0000u);
                uint32_t lo = pack2(r0, r1);
                int kc = c >> 6, f2 = (c & 63) >> 1;
                int word = kc * 4096 + b * 32 + (f2 ^ ((b & 7) << 2));
                hp[word]        = hi;
                hp[word + 2048] = lo;
            }
        }
        gsync();
    }
}

extern "C" void kernel_launch(void* const* d_in, const int* in_sizes, int n_in,
                              void* d_out, int out_size)
{
    const float* x    = (const float*)d_in[0];
    const float* mem  = (const float*)d_in[1];
    const float* Wk   = (const float*)d_in[2];
    const float* bk   = (const float*)d_in[3];
    const float* Wri  = (const float*)d_in[4];
    const float* bri  = (const float*)d_in[5];
    const float* Wih  = (const float*)d_in[6];
    const float* Whh  = (const float*)d_in[7];
    const float* bih  = (const float*)d_in[8];
    const float* bhh  = (const float*)d_in[9];
    const float* Wout = (const float*)d_in[10];
    const float* bout = (const float*)d_in[11];

    static int once = 0;
    const int smem_bytes = 3 * STAGE_BYTES;   // 147,456
    if (!once) {
        cudaFuncSetAttribute(ntm_persist,
                             cudaFuncAttributeMaxDynamicSharedMemorySize,
                             smem_bytes);
        once = 1;
    }

    ntm_persist<<<NB, NT, smem_bytes>>>(x, mem, Wk, bk, Wri, bri, Wih, Whh,
                                        bih, bhh, Wout, bout, (float*)d_out);
}